// round 16
// baseline (speedup 1.0000x reference)
#include <cuda_runtime.h>

#define EMB 100
#define BOT 5
#define B_  128
#define S_  2048
#define V_  50257
#define HPW ((((V_ + 3) / 4) + 3) & ~3)   // u8-packed hist words, 16B multiple
#define FULLMASK 0xffffffffu

// Scratch: overwritten by K1 before K2 reads it, every launch. No invariants.
__device__ float g_hp[B_][4][8];   // per-quarter fc1 partials (5 used)
__device__ float g_zp[B_][4];      // per-quarter Z partials

// ---------------------------------------------------------------------------
// K1: count-free weighted gather. 4 CTAs per row x 128 threads.
// No histogram, no atomics, no zeroing -- pure LDG pipeline.
// ---------------------------------------------------------------------------
__global__ void __launch_bounds__(128)
k1_gather(const int* __restrict__ x, const float* __restrict__ we,
          const float* __restrict__ idf, const float* __restrict__ fc1w)
{
    __shared__ float stage[4 * 256];   // per-warp 64 float4 (offset,idf) pairs
    __shared__ float zp[4];
    __shared__ float hw[4 * 6];

    const int tid  = threadIdx.x;
    const int warp = tid >> 5;
    const int lane = tid & 31;
    const int b    = blockIdx.x >> 2;
    const int q    = blockIdx.x & 3;

    // quarter-row: 512 tokens; warp owns 128, lane holds 4 (one LDG.128)
    const int* xr = x + b * S_ + (q << 9);
    const int4 t4 = *(const int4*)(xr + (warp << 7) + (lane << 2));

    const float i0 = __ldg(&idf[t4.x]);
    const float i1 = __ldg(&idf[t4.y]);
    const float i2 = __ldg(&idf[t4.z]);
    const float i3 = __ldg(&idf[t4.w]);

    float4* stW = (float4*)(stage + (warp << 8));
    stW[(lane << 1)]     = make_float4(__int_as_float(t4.x * (EMB * 4)), i0,
                                       __int_as_float(t4.y * (EMB * 4)), i1);
    stW[(lane << 1) + 1] = make_float4(__int_as_float(t4.z * (EMB * 4)), i2,
                                       __int_as_float(t4.w * (EMB * 4)), i3);

    float z = (i0 + i1) + (i2 + i3);
    #pragma unroll
    for (int o = 16; o; o >>= 1) z += __shfl_xor_sync(FULLMASK, z, o);
    if (lane == 0) zp[warp] = z;
    __syncwarp();                       // own strip ready

    const bool active = lane < (EMB / 4);
    const int  eoff   = lane << 4;
    const char* web = (const char*)we;
    float4 acc0 = make_float4(0.f, 0.f, 0.f, 0.f);
    float4 acc1 = make_float4(0.f, 0.f, 0.f, 0.f);

    #pragma unroll 2
    for (int kk = 0; kk < 64; kk += 4) {
        const float4 q0 = stW[kk];
        const float4 q1 = stW[kk + 1];
        const float4 q2 = stW[kk + 2];
        const float4 q3 = stW[kk + 3];
        if (active) {
            const float4 ea = *(const float4*)(web + __float_as_int(q0.x) + eoff);
            const float4 eb = *(const float4*)(web + __float_as_int(q0.z) + eoff);
            const float4 ec = *(const float4*)(web + __float_as_int(q1.x) + eoff);
            const float4 ed = *(const float4*)(web + __float_as_int(q1.z) + eoff);
            const float4 ee = *(const float4*)(web + __float_as_int(q2.x) + eoff);
            const float4 ef = *(const float4*)(web + __float_as_int(q2.z) + eoff);
            const float4 eg = *(const float4*)(web + __float_as_int(q3.x) + eoff);
            const float4 eh = *(const float4*)(web + __float_as_int(q3.z) + eoff);
            acc0.x += q0.y * ea.x; acc0.y += q0.y * ea.y; acc0.z += q0.y * ea.z; acc0.w += q0.y * ea.w;
            acc1.x += q0.w * eb.x; acc1.y += q0.w * eb.y; acc1.z += q0.w * eb.z; acc1.w += q0.w * eb.w;
            acc0.x += q1.y * ec.x; acc0.y += q1.y * ec.y; acc0.z += q1.y * ec.z; acc0.w += q1.y * ec.w;
            acc1.x += q1.w * ed.x; acc1.y += q1.w * ed.y; acc1.z += q1.w * ed.z; acc1.w += q1.w * ed.w;
            acc0.x += q2.y * ee.x; acc0.y += q2.y * ee.y; acc0.z += q2.y * ee.z; acc0.w += q2.y * ee.w;
            acc1.x += q2.w * ef.x; acc1.y += q2.w * ef.y; acc1.z += q2.w * ef.z; acc1.w += q2.w * ef.w;
            acc0.x += q3.y * eg.x; acc0.y += q3.y * eg.y; acc0.z += q3.y * eg.z; acc0.w += q3.y * eg.w;
            acc1.x += q3.w * eh.x; acc1.y += q3.w * eh.y; acc1.z += q3.w * eh.z; acc1.w += q3.w * eh.w;
        }
    }

    // fc1 partials (doc never materialized)
    acc0.x += acc1.x; acc0.y += acc1.y; acc0.z += acc1.z; acc0.w += acc1.w;
    #pragma unroll
    for (int j = 0; j < BOT; j++) {
        float s = 0.f;
        if (active) {
            const float4 w1 = *(const float4*)(fc1w + j * EMB + (lane << 2));
            s = acc0.x * w1.x + acc0.y * w1.y + acc0.z * w1.z + acc0.w * w1.w;
        }
        #pragma unroll
        for (int o = 16; o; o >>= 1) s += __shfl_xor_sync(FULLMASK, s, o);
        if (lane == 0) hw[warp * 6 + j] = s;
    }
    __syncthreads();

    if (tid < BOT) {
        float h = 0.f;
        #pragma unroll
        for (int w = 0; w < 4; w++) h += hw[w * 6 + tid];
        g_hp[b][q][tid] = h;                       // overwrite (no clearing)
    }
    if (tid == BOT) {
        float zz = zp[0] + zp[1] + zp[2] + zp[3];
        g_zp[b][q] = zz;
    }
}

// ---------------------------------------------------------------------------
// K2: histogram + duplicate correction + MLP. One CTA per row, 1024 threads.
// Smem: u8-packed hist (HPW words) + 32 per-warp dup queues + reduction bufs.
// ---------------------------------------------------------------------------
__global__ void __launch_bounds__(1024, 1)
k2_correct(const int* __restrict__ x, const float* __restrict__ we,
           const float* __restrict__ idf,
           const float* __restrict__ fc1w, const float* __restrict__ fc1b,
           const float* __restrict__ fc2w, const float* __restrict__ fc2b,
           float* __restrict__ out)
{
    extern __shared__ unsigned int smem[];
    unsigned int* hist = smem;                  // HPW words
    int2*  queue = (int2*)(hist + HPW);         // 32 warps * 64 entries
    float* hw    = (float*)(queue + 32 * 64);   // 32*6
    float* hv    = hw + 32 * 6;                 // 8

    const int tid  = threadIdx.x;
    const int warp = tid >> 5;
    const int lane = tid & 31;
    const int b    = blockIdx.x;

    // warp owns tokens [64w, 64w+64); lane holds 2 (one LDG.64)
    const int2 tt = *(const int2*)(x + b * S_ + (tid << 1));

    // zero histogram (vectorized)
    uint4* h4 = (uint4*)hist;
    const uint4 z4 = make_uint4(0u, 0u, 0u, 0u);
    for (int i = tid; i < (HPW >> 2); i += 1024) h4[i] = z4;
    __syncthreads();

    atomicAdd(&hist[tt.x >> 2], 1u << ((tt.x & 3) << 3));
    atomicAdd(&hist[tt.y >> 2], 1u << ((tt.y & 3) << 3));
    __syncthreads();

    const unsigned n0 = (hist[tt.x >> 2] >> ((tt.x & 3) << 3)) & 0xFFu;
    const unsigned n1 = (hist[tt.y >> 2] >> ((tt.y & 3) << 3)) & 0xFFu;

    // compact duplicates into this warp's queue: (token, count-1)
    int2* qW = queue + (warp << 6);
    int qlen = 0;
    {
        const unsigned lt = (1u << lane) - 1u;
        unsigned m;
        m = __ballot_sync(FULLMASK, n0 > 1);
        if (n0 > 1) qW[qlen + __popc(m & lt)] = make_int2(tt.x, (int)(n0 - 1));
        qlen += __popc(m);
        m = __ballot_sync(FULLMASK, n1 > 1);
        if (n1 > 1) qW[qlen + __popc(m & lt)] = make_int2(tt.y, (int)(n1 - 1));
        qlen += __popc(m);
    }
    __syncwarp();

    // correction gather: ~2-3 entries per warp expected
    const bool active = lane < (EMB / 4);
    const int  eoff   = lane << 4;
    const char* web = (const char*)we;
    float4 acc = make_float4(0.f, 0.f, 0.f, 0.f);
    for (int j = 0; j < qlen; j++) {
        const int2 e = qW[j];
        const float coef = (float)e.y * __ldg(&idf[e.x]);
        if (active) {
            const float4 ev = *(const float4*)(web + e.x * (EMB * 4) + eoff);
            acc.x += coef * ev.x; acc.y += coef * ev.y;
            acc.z += coef * ev.z; acc.w += coef * ev.w;
        }
    }

    // fc1 partials of the correction term
    #pragma unroll
    for (int j = 0; j < BOT; j++) {
        float s = 0.f;
        if (active) {
            const float4 w1 = *(const float4*)(fc1w + j * EMB + (lane << 2));
            s = acc.x * w1.x + acc.y * w1.y + acc.z * w1.z + acc.w * w1.w;
        }
        #pragma unroll
        for (int o = 16; o; o >>= 1) s += __shfl_xor_sync(FULLMASK, s, o);
        if (lane == 0) hw[warp * 6 + j] = s;
    }
    __syncthreads();

    // combine: 32 warp partials + 4 K1 quarters, fixed order; invZ; bias
    if (tid < BOT) {
        float h = 0.f;
        #pragma unroll
        for (int w = 0; w < 32; w++) h += hw[w * 6 + tid];
        #pragma unroll
        for (int qq = 0; qq < 4; qq++) h += g_hp[b][qq][tid];
        const float zz = ((g_zp[b][0] + g_zp[b][1]) + (g_zp[b][2] + g_zp[b][3]));
        hv[tid] = h * (1.0f / zz) + __ldg(&fc1b[tid]);
    }
    __syncthreads();

    if (tid < EMB) {
        float o = __ldg(&fc2b[tid]);
        #pragma unroll
        for (int j = 0; j < BOT; j++) o += hv[j] * __ldg(&fc2w[tid * BOT + j]);
        out[b * EMB + tid] = o;
    }
}

extern "C" void kernel_launch(void* const* d_in, const int* in_sizes, int n_in,
                              void* d_out, int out_size)
{
    const int*   x    = (const int*)  d_in[0];   // [B,S] int32 token ids
    const float* we   = (const float*)d_in[1];   // [V,EMB]
    const float* idf  = (const float*)d_in[2];   // [V]
    const float* fc1w = (const float*)d_in[3];   // [BOT,EMB]
    const float* fc1b = (const float*)d_in[4];   // [BOT]
    const float* fc2w = (const float*)d_in[5];   // [EMB,BOT]
    const float* fc2b = (const float*)d_in[6];   // [EMB]
    float* out = (float*)d_out;                  // [B,EMB]

    size_t smem2 = (size_t)HPW * 4 + 32 * 64 * sizeof(int2)
                 + (32 * 6 + 8) * sizeof(float);
    cudaFuncSetAttribute(k2_correct,
                         cudaFuncAttributeMaxDynamicSharedMemorySize,
                         (int)smem2);

    k1_gather<<<4 * B_, 128>>>(x, we, idf, fc1w);
    k2_correct<<<B_, 1024, smem2>>>(x, we, idf, fc1w, fc1b, fc2w, fc2b, out);
}

// round 17
// speedup vs baseline: 1.5702x; 1.5702x over previous
#include <cuda_runtime.h>

#define EMB 100
#define BOT 5
#define NT  512
#define FULLMASK 0xffffffffu

// One CTA per document row, 512 threads.
// doc = invZ * sum_s idf_s * (1 + 2*old_s) * emb_s
// where old_s is the atomicAdd return (prior count of that token): over the
// o occurrences of a token the old values are {0..o-1}, so the summed
// coefficient is o^2 * idf -- exactly tf*idf per occurrence. No count
// re-read, no second pass, no duplicate queue.
__global__ void __launch_bounds__(NT, 1)
doc_model_kernel(const int* __restrict__ x,
                 const float* __restrict__ we,
                 const float* __restrict__ idf,
                 const float* __restrict__ fc1w,
                 const float* __restrict__ fc1b,
                 const float* __restrict__ fc2w,
                 const float* __restrict__ fc2b,
                 float* __restrict__ out,
                 int S, int V)
{
    extern __shared__ unsigned int smem[];
    const int histPadW = ((((V + 3) >> 2) + 3) & ~3);   // u8-packed, 16B mult
    unsigned int* hist = smem;                    // histPadW words
    float* stage = (float*)(hist + histPadW);     // 16 warps * 256 floats
    float* zp    = stage + 16 * 256;              // 16
    float* hw    = zp + 16;                       // 16*6 fc1 warp partials
    float* hv    = hw + 16 * 6;                   // 8

    const int tid  = threadIdx.x;
    const int warp = tid >> 5;
    const int lane = tid & 31;

    // ---- token load (one LDG.128): warp w owns tokens [128w, 128w+128),
    // lane l holds tokens 128w + 4l + {0..3}. Latency hides behind zeroing.
    const int* xr = x + (long long)blockIdx.x * S;
    const int4 t4 = *(const int4*)(xr + (warp << 7) + (lane << 2));

    // ---- zero histogram (vectorized, u8-packed) ----
    uint4* h4 = (uint4*)hist;
    const uint4 z4 = make_uint4(0u, 0u, 0u, 0u);
    for (int i = tid; i < (histPadW >> 2); i += NT) h4[i] = z4;

    // idf gathers: independent, issue before the barrier
    const float i0 = __ldg(&idf[t4.x]);
    const float i1 = __ldg(&idf[t4.y]);
    const float i2 = __ldg(&idf[t4.z]);
    const float i3 = __ldg(&idf[t4.w]);
    __syncthreads();                               // hist zeroed

    // ---- histogram atomics WITH RETURN: old byte = prior count of my token
    const int sh0 = (t4.x & 3) << 3, sh1 = (t4.y & 3) << 3;
    const int sh2 = (t4.z & 3) << 3, sh3 = (t4.w & 3) << 3;
    const unsigned r0 = atomicAdd(&hist[t4.x >> 2], 1u << sh0);
    const unsigned r1 = atomicAdd(&hist[t4.y >> 2], 1u << sh1);
    const unsigned r2 = atomicAdd(&hist[t4.z >> 2], 1u << sh2);
    const unsigned r3 = atomicAdd(&hist[t4.w >> 2], 1u << sh3);
    const float c0 = i0 * (float)(1 + 2 * (int)((r0 >> sh0) & 0xFFu));
    const float c1 = i1 * (float)(1 + 2 * (int)((r1 >> sh1) & 0xFFu));
    const float c2 = i2 * (float)(1 + 2 * (int)((r2 >> sh2) & 0xFFu));
    const float c3 = i3 * (float)(1 + 2 * (int)((r3 >> sh3) & 0xFFu));

    // ---- stage (byte-offset, coef) pairs (warp-private strips) ----
    float4* stW = (float4*)(stage + (warp << 8));
    stW[(lane << 1)]     = make_float4(__int_as_float(t4.x * (EMB * 4)), c0,
                                       __int_as_float(t4.y * (EMB * 4)), c1);
    stW[(lane << 1) + 1] = make_float4(__int_as_float(t4.z * (EMB * 4)), c2,
                                       __int_as_float(t4.w * (EMB * 4)), c3);

    // Z partial (idf only -- normalization does not involve counts)
    float z = (i0 + i1) + (i2 + i3);
    #pragma unroll
    for (int o = 16; o; o >>= 1) z += __shfl_xor_sync(FULLMASK, z, o);
    if (lane == 0) zp[warp] = z;
    __syncwarp();                                  // own strip ready

    // ---- SINGLE GATHER PASS (proven R7/R12 pipeline) ----
    const bool active = lane < (EMB / 4);
    const int  eoff   = lane << 4;
    const char* web = (const char*)we;
    float4 acc0 = make_float4(0.f, 0.f, 0.f, 0.f);
    float4 acc1 = make_float4(0.f, 0.f, 0.f, 0.f);

    #pragma unroll 2
    for (int kk = 0; kk < 64; kk += 4) {
        const float4 q0 = stW[kk];
        const float4 q1 = stW[kk + 1];
        const float4 q2 = stW[kk + 2];
        const float4 q3 = stW[kk + 3];
        if (active) {
            const float4 ea = *(const float4*)(web + __float_as_int(q0.x) + eoff);
            const float4 eb = *(const float4*)(web + __float_as_int(q0.z) + eoff);
            const float4 ec = *(const float4*)(web + __float_as_int(q1.x) + eoff);
            const float4 ed = *(const float4*)(web + __float_as_int(q1.z) + eoff);
            const float4 ee = *(const float4*)(web + __float_as_int(q2.x) + eoff);
            const float4 ef = *(const float4*)(web + __float_as_int(q2.z) + eoff);
            const float4 eg = *(const float4*)(web + __float_as_int(q3.x) + eoff);
            const float4 eh = *(const float4*)(web + __float_as_int(q3.z) + eoff);
            acc0.x += q0.y * ea.x; acc0.y += q0.y * ea.y; acc0.z += q0.y * ea.z; acc0.w += q0.y * ea.w;
            acc1.x += q0.w * eb.x; acc1.y += q0.w * eb.y; acc1.z += q0.w * eb.z; acc1.w += q0.w * eb.w;
            acc0.x += q1.y * ec.x; acc0.y += q1.y * ec.y; acc0.z += q1.y * ec.z; acc0.w += q1.y * ec.w;
            acc1.x += q1.w * ed.x; acc1.y += q1.w * ed.y; acc1.z += q1.w * ed.z; acc1.w += q1.w * ed.w;
            acc0.x += q2.y * ee.x; acc0.y += q2.y * ee.y; acc0.z += q2.y * ee.z; acc0.w += q2.y * ee.w;
            acc1.x += q2.w * ef.x; acc1.y += q2.w * ef.y; acc1.z += q2.w * ef.z; acc1.w += q2.w * ef.w;
            acc0.x += q3.y * eg.x; acc0.y += q3.y * eg.y; acc0.z += q3.y * eg.z; acc0.w += q3.y * eg.w;
            acc1.x += q3.w * eh.x; acc1.y += q3.w * eh.y; acc1.z += q3.w * eh.z; acc1.w += q3.w * eh.w;
        }
    }

    // ---- fused fc1: warp-level dot products (doc never materialized) ----
    acc0.x += acc1.x; acc0.y += acc1.y; acc0.z += acc1.z; acc0.w += acc1.w;
    #pragma unroll
    for (int j = 0; j < BOT; j++) {
        float s = 0.f;
        if (active) {
            const float4 w1v = *(const float4*)(fc1w + j * EMB + (lane << 2));
            s = acc0.x * w1v.x + acc0.y * w1v.y + acc0.z * w1v.z + acc0.w * w1v.w;
        }
        #pragma unroll
        for (int o = 16; o; o >>= 1) s += __shfl_xor_sync(FULLMASK, s, o);
        if (lane == 0) hw[warp * 6 + j] = s;
    }
    __syncthreads();   // hw + zp visible

    // 5 threads: fixed-order 16-way sum, scale by invZ, add bias
    if (tid < BOT) {
        float zz = 0.f;
        #pragma unroll
        for (int i = 0; i < 16; i++) zz += zp[i];
        float h = 0.f;
        #pragma unroll
        for (int w = 0; w < 16; w++) h += hw[w * 6 + tid];
        hv[tid] = h * (1.0f / zz) + __ldg(&fc1b[tid]);
    }
    __syncthreads();

    // 100 threads: fc2
    if (tid < EMB) {
        float o = __ldg(&fc2b[tid]);
        #pragma unroll
        for (int j = 0; j < BOT; j++) o += hv[j] * __ldg(&fc2w[tid * BOT + j]);
        out[(long long)blockIdx.x * EMB + tid] = o;
    }
}

extern "C" void kernel_launch(void* const* d_in, const int* in_sizes, int n_in,
                              void* d_out, int out_size)
{
    const int*   x    = (const int*)  d_in[0];   // [B,S] int32 token ids
    const float* we   = (const float*)d_in[1];   // [V,EMB]
    const float* idf  = (const float*)d_in[2];   // [V]
    const float* fc1w = (const float*)d_in[3];   // [BOT,EMB]
    const float* fc1b = (const float*)d_in[4];   // [BOT]
    const float* fc2w = (const float*)d_in[5];   // [EMB,BOT]
    const float* fc2b = (const float*)d_in[6];   // [EMB]
    float* out = (float*)d_out;                  // [B,EMB]

    const int V = in_sizes[2];
    const int B = out_size / EMB;
    const int S = in_sizes[0] / B;

    const int histPadW = ((((V + 3) >> 2) + 3) & ~3);
    size_t smem_bytes = (size_t)histPadW * 4
                      + (size_t)(16 * 256 + 16 + 16 * 6 + 8) * 4;

    cudaFuncSetAttribute(doc_model_kernel,
                         cudaFuncAttributeMaxDynamicSharedMemorySize,
                         (int)smem_bytes);

    doc_model_kernel<<<B, NT, smem_bytes>>>(x, we, idf, fc1w, fc1b, fc2w, fc2b,
                                            out, S, V);
}